// round 14
// baseline (speedup 1.0000x reference)
#include <cuda_runtime.h>
#include <cuda_fp16.h>
#include <cstdint>

// HDCHead: scores = sign(x@proj) @ class_hv ; outputs (scores[16384,1000], hv_bin[16384,8192]) f32.
// R13: R12 structure (single-pass fp16, 128x128 CTA, K-chunk 128, 3 stages) but 512 threads
// (16 warps, warp tile 32x32) for 4 warps/SMSP issue coverage. TAU=0.05 fixup; fp16 GEMM2.

static constexpr int M1 = 16384, K1 = 2048, N1 = 8192, NC = 1000, NCP = 1024;
static constexpr long long SCORES_ELEMS = (long long)M1 * NC;
static constexpr float TAU = 0.05f;
static constexpr uint32_t FIXCAP = 1u << 21;

// -------- scratch (device globals) --------
__device__ __align__(256) __half g_xh[(size_t)M1 * K1];      //  67MB
__device__ __align__(256) __half g_projT[(size_t)N1 * K1];   //  33MB  [N1][K1]
__device__ __align__(256) __half g_chvT[(size_t)NCP * N1];   //  17MB  [1024][8192]
__device__ __align__(256) __half g_hvb[(size_t)M1 * N1];     // 268MB  fp16 sign
__device__ uint32_t g_fixcnt;
__device__ uint32_t g_fixq[FIXCAP];

// -------- PTX helpers --------
__device__ __forceinline__ uint32_t smem_u32(const void* p) {
    uint32_t a;
    asm("{ .reg .u64 t; cvta.to.shared.u64 t, %1; cvt.u32.u64 %0, t; }" : "=r"(a) : "l"(p));
    return a;
}
__device__ __forceinline__ void cp16(uint32_t d, const void* s) {
    asm volatile("cp.async.cg.shared.global [%0], [%1], 16;" :: "r"(d), "l"(s));
}
#define CP_COMMIT() asm volatile("cp.async.commit_group;" ::: "memory")
#define CP_WAIT(n)  asm volatile("cp.async.wait_group %0;" :: "n"(n) : "memory")
#define SWZ(o) ((o) ^ (((o) >> 3) & 0x70))

__device__ __forceinline__ void ldsm4(uint32_t& r0, uint32_t& r1, uint32_t& r2, uint32_t& r3,
                                      uint32_t addr) {
    asm volatile("ldmatrix.sync.aligned.m8n8.x4.shared.b16 {%0,%1,%2,%3}, [%4];"
                 : "=r"(r0), "=r"(r1), "=r"(r2), "=r"(r3) : "r"(addr));
}
__device__ __forceinline__ void mma16816(float* d, const uint32_t* a, const uint32_t* b) {
    asm volatile("mma.sync.aligned.m16n8k16.row.col.f32.f16.f16.f32 "
                 "{%0,%1,%2,%3}, {%4,%5,%6,%7}, {%8,%9}, {%0,%1,%2,%3};"
                 : "+f"(d[0]), "+f"(d[1]), "+f"(d[2]), "+f"(d[3])
                 : "r"(a[0]), "r"(a[1]), "r"(a[2]), "r"(a[3]), "r"(b[0]), "r"(b[1]));
}

// -------- prep kernels --------
__global__ __launch_bounds__(256) void k_convert_x(const float4* __restrict__ x4) {
    if (blockIdx.x == 0 && threadIdx.x == 0) g_fixcnt = 0;
    size_t i = (size_t)blockIdx.x * 256 + threadIdx.x;
    float4 v = x4[i];
    __half2* ph = reinterpret_cast<__half2*>(g_xh);
    ph[i * 2 + 0] = __floats2half2_rn(v.x, v.y);
    ph[i * 2 + 1] = __floats2half2_rn(v.z, v.w);
}

// proj f32 [K1][N1] -> g_projT fp16 [N1][K1]
__global__ __launch_bounds__(256) void k_transpose_proj(const float* __restrict__ src) {
    __shared__ float t[32][33];
    int c0 = blockIdx.x * 32, r0 = blockIdx.y * 32;
    int tx = threadIdx.x & 31, ty = threadIdx.x >> 5;
#pragma unroll
    for (int j = 0; j < 4; ++j)
        t[ty + j * 8][tx] = src[(size_t)(r0 + ty + j * 8) * N1 + c0 + tx];
    __syncthreads();
#pragma unroll
    for (int j = 0; j < 4; ++j) {
        int c = c0 + ty + j * 8;
        g_projT[(size_t)c * K1 + r0 + tx] = __float2half_rn(t[tx][ty + j * 8]);
    }
}

// chv f32 [N1][NC] -> g_chvT fp16 [NCP][N1], rows >= NC zero
__global__ __launch_bounds__(256) void k_transpose_chv(const float* __restrict__ src) {
    __shared__ float t[32][33];
    int c0 = blockIdx.x * 32, r0 = blockIdx.y * 32;
    int tx = threadIdx.x & 31, ty = threadIdx.x >> 5;
#pragma unroll
    for (int j = 0; j < 4; ++j) {
        int r = r0 + ty + j * 8, c = c0 + tx;
        t[ty + j * 8][tx] = (c < NC) ? src[(size_t)r * NC + c] : 0.f;
    }
    __syncthreads();
#pragma unroll
    for (int j = 0; j < 4; ++j) {
        int c = c0 + ty + j * 8;
        g_chvT[(size_t)c * N1 + r0 + tx] = __float2half_rn(t[tx][ty + j * 8]);
    }
}

// -------- fp16 HMMA GEMM: CTA 128x128, 512 threads, warps 4x4 (32x32), K-chunk 128, 3 stages --------
// MODE 1: hv = x @ projT^T -> sign to outF (f32) + g_hvb (fp16); queue |hv| < TAU
// MODE 2: scores = g_hvb @ chvT^T -> guarded f32 store (cols < NC)
template<int MODE>
__global__ __launch_bounds__(512, 1) void hd_gemm(float* __restrict__ outF) {
    constexpr int  KTOT = (MODE == 1) ? K1 : N1;
    constexpr int  PANEL = 128 * 128;              // 128 rows x 64 fp16 SW128 panel (16KB)
    constexpr int  A_BYTES = 2 * PANEL;
    constexpr int  STAGE_BYTES = 2 * A_BYTES;      // 64KB
    constexpr int  STAGES = 3;
    constexpr int  C = KTOT / 128;                 // 16 / 64

    extern __shared__ char smem[];
    const int tid = threadIdx.x;
    const int wid = tid >> 5, lane = tid & 31;
    const int wm = wid & 3;                        // 4 warps over M -> 32 rows each
    const int wn = wid >> 2;                       // 4 warps over N -> 32 cols each
    const int m0 = blockIdx.y * 128;
    const int n0 = blockIdx.x * 128;
    const uint32_t sb = smem_u32(smem);

    const __half* __restrict__ Am = (MODE == 1) ? g_xh : g_hvb;
    const __half* __restrict__ Bt = (MODE == 1) ? g_projT : g_chvT;

    float acc[2][4][4];
#pragma unroll
    for (int i = 0; i < 2; ++i)
#pragma unroll
        for (int j = 0; j < 4; ++j)
#pragma unroll
            for (int q = 0; q < 4; ++q) acc[i][j][q] = 0.f;

    // load one K=128 chunk (4096 x 16B): 512 threads x 8 cp16
    auto load_stage = [&](int chunk, int st) {
        uint32_t base = sb + st * STAGE_BYTES;
#pragma unroll
        for (int p = 0; p < 2; ++p) {
#pragma unroll
            for (int i = 0; i < 2; ++i) {          // A panel p: 1024 words
                int u = tid + i * 512, r = u >> 3, cc = u & 7;
                cp16(base + p * PANEL + SWZ(r * 128 + cc * 16),
                     Am + (size_t)(m0 + r) * KTOT + chunk * 128 + p * 64 + cc * 8);
            }
        }
#pragma unroll
        for (int p = 0; p < 2; ++p) {
#pragma unroll
            for (int i = 0; i < 2; ++i) {          // B panel p
                int u = tid + i * 512, r = u >> 3, cc = u & 7;
                cp16(base + A_BYTES + p * PANEL + SWZ(r * 128 + cc * 16),
                     Bt + (size_t)(n0 + r) * KTOT + chunk * 128 + p * 64 + cc * 8);
            }
        }
    };

    for (int p = 0; p < STAGES - 1; ++p) { load_stage(p, p); CP_COMMIT(); }

    const int a_row = lane & 15;
    const int a_cb  = (lane >> 4) << 4;
    const int b_row = ((lane >> 4) << 3) + (lane & 7);
    const int b_cb  = ((lane >> 3) & 1) << 4;

    for (int c = 0; c < C; ++c) {
        int st = c % STAGES;
        if (c < C - 1) { CP_WAIT(1); } else { CP_WAIT(0); }
        __syncthreads();
        int nxt = c + STAGES - 1;
        if (nxt < C) { load_stage(nxt, nxt % STAGES); CP_COMMIT(); }

        uint32_t aS = sb + st * STAGE_BYTES;
        uint32_t bS = aS + A_BYTES;
#pragma unroll
        for (int ks = 0; ks < 8; ++ks) {           // 8 x k16 within K=128 chunk
            uint32_t aBase = aS + (ks >> 2) * PANEL;
            uint32_t bBase = bS + (ks >> 2) * PANEL;
            int kb = (ks & 3) * 32;
            uint32_t bfr[2][4];
#pragma unroll
            for (int j2 = 0; j2 < 2; ++j2) {       // 2 x n16 = warp n32
                int nrow = wn * 32 + j2 * 16 + b_row;
                ldsm4(bfr[j2][0], bfr[j2][1], bfr[j2][2], bfr[j2][3],
                      bBase + SWZ(nrow * 128 + kb + b_cb));
            }
#pragma unroll
            for (int i = 0; i < 2; ++i) {          // 2 x m16 = warp m32
                int mrow = wm * 32 + i * 16 + a_row;
                uint32_t afr[4];
                ldsm4(afr[0], afr[1], afr[2], afr[3],
                      aBase + SWZ(mrow * 128 + kb + a_cb));
#pragma unroll
                for (int j = 0; j < 4; ++j)
                    mma16816(acc[i][j], afr, &bfr[j >> 1][(j & 1) * 2]);
            }
        }
        __syncthreads();
    }

    // -------- epilogue --------
    const int gid = lane >> 2, tid4 = lane & 3;
#pragma unroll
    for (int i = 0; i < 2; ++i) {
#pragma unroll
        for (int half = 0; half < 2; ++half) {
            size_t row = m0 + wm * 32 + i * 16 + gid + half * 8;
#pragma unroll
            for (int j = 0; j < 4; ++j) {
                int col = n0 + wn * 32 + j * 8 + tid4 * 2;
                float v0 = acc[i][j][half * 2 + 0];
                float v1 = acc[i][j][half * 2 + 1];
                if (MODE == 1) {
                    float s0 = (v0 >= 0.f) ? 1.f : -1.f;
                    float s1 = (v1 >= 0.f) ? 1.f : -1.f;
                    *reinterpret_cast<float2*>(outF + row * (size_t)N1 + col) =
                        make_float2(s0, s1);
                    *reinterpret_cast<__half2*>(g_hvb + row * (size_t)N1 + col) =
                        __floats2half2_rn(s0, s1);
                    if (fabsf(v0) < TAU) {
                        uint32_t idx = atomicAdd(&g_fixcnt, 1u);
                        if (idx < FIXCAP) g_fixq[idx] = ((uint32_t)row << 13) | (uint32_t)col;
                    }
                    if (fabsf(v1) < TAU) {
                        uint32_t idx = atomicAdd(&g_fixcnt, 1u);
                        if (idx < FIXCAP) g_fixq[idx] = ((uint32_t)row << 13) | (uint32_t)(col + 1);
                    }
                } else {
                    if (col + 1 < NC) {
                        *reinterpret_cast<float2*>(outF + row * (size_t)NC + col) =
                            make_float2(v0, v1);
                    } else if (col < NC) {
                        outF[row * (size_t)NC + col] = v0;
                    }
                }
            }
        }
    }
}

// -------- exact fixup: warp per queued element, Kahan fp32 dot over K1 --------
__global__ __launch_bounds__(128) void k_fixup(const float* __restrict__ x,
                                               float* __restrict__ hvf32) {
    uint32_t total = g_fixcnt;
    if (total > FIXCAP) total = FIXCAP;
    int gw = (blockIdx.x * 128 + threadIdx.x) >> 5;
    int lane = threadIdx.x & 31;
    int nw = (gridDim.x * 128) >> 5;
    for (uint32_t w = gw; w < total; w += nw) {
        uint32_t e = g_fixq[w];
        uint32_t row = e >> 13, col = e & 8191u;
        const float* xr = x + (size_t)row * K1;
        const __half* pr = g_projT + (size_t)col * K1;
        float s = 0.f, comp = 0.f;
#pragma unroll 4
        for (int j = 0; j < K1 / 32; ++j) {
            int k = lane + j * 32;
            float t = xr[k] * __half2float(pr[k]);
            float y = t - comp;
            float u = s + y;
            comp = (u - s) - y;
            s = u;
        }
#pragma unroll
        for (int o = 16; o > 0; o >>= 1) s += __shfl_xor_sync(0xFFFFFFFFu, s, o);
        if (lane == 0) {
            float sg = (s >= 0.f) ? 1.f : -1.f;
            hvf32[(size_t)row * N1 + col] = sg;
            g_hvb[(size_t)row * N1 + col] = __float2half_rn(sg);
        }
    }
}

// -------- launch --------
extern "C" void kernel_launch(void* const* d_in, const int* in_sizes, int n_in,
                              void* d_out, int out_size)
{
    const float* x    = (const float*)d_in[0];
    const float* proj = (const float*)d_in[1];
    const float* chv  = (const float*)d_in[2];
    float* scores = (float*)d_out;
    float* hvf32  = (float*)d_out + SCORES_ELEMS;

    constexpr int SMB = 3 * 4 * 128 * 128;   // 196608 (3 stages x 64KB)
    cudaFuncSetAttribute(hd_gemm<1>, cudaFuncAttributeMaxDynamicSharedMemorySize, SMB);
    cudaFuncSetAttribute(hd_gemm<2>, cudaFuncAttributeMaxDynamicSharedMemorySize, SMB);

    k_convert_x<<<32768, 256>>>((const float4*)x);
    k_transpose_proj<<<dim3(N1 / 32, K1 / 32), 256>>>(proj);
    k_transpose_chv<<<dim3(NCP / 32, N1 / 32), 256>>>(chv);

    hd_gemm<1><<<dim3(N1 / 128, M1 / 128), 512, SMB>>>(hvf32);   // single fp16 pass
    k_fixup<<<2048, 128>>>(x, hvf32);
    hd_gemm<2><<<dim3(NCP / 128, M1 / 128), 512, SMB>>>(scores);
}

// round 15
// speedup vs baseline: 1.1948x; 1.1948x over previous
#include <cuda_runtime.h>
#include <cuda_fp16.h>
#include <cstdint>

// HDCHead: scores = sign(x@proj) @ class_hv ; outputs (scores[16384,1000], hv_bin[16384,8192]) f32.
// R14: single-pass fp16 HMMA, 128x128 CTA / warp 64x32 (best ratio), K-chunk 64, 3 stages
// (96KB smem) + __launch_bounds__(256,2) -> 2 CTAs/SM for cross-CTA latency hiding.
// TAU=0.05 exact fixup; fp16 GEMM2 (bit-exact).

static constexpr int M1 = 16384, K1 = 2048, N1 = 8192, NC = 1000, NCP = 1024;
static constexpr long long SCORES_ELEMS = (long long)M1 * NC;
static constexpr float TAU = 0.05f;
static constexpr uint32_t FIXCAP = 1u << 21;

// -------- scratch (device globals) --------
__device__ __align__(256) __half g_xh[(size_t)M1 * K1];      //  67MB
__device__ __align__(256) __half g_projT[(size_t)N1 * K1];   //  33MB  [N1][K1]
__device__ __align__(256) __half g_chvT[(size_t)NCP * N1];   //  17MB  [1024][8192]
__device__ __align__(256) __half g_hvb[(size_t)M1 * N1];     // 268MB  fp16 sign
__device__ uint32_t g_fixcnt;
__device__ uint32_t g_fixq[FIXCAP];

// -------- PTX helpers --------
__device__ __forceinline__ uint32_t smem_u32(const void* p) {
    uint32_t a;
    asm("{ .reg .u64 t; cvta.to.shared.u64 t, %1; cvt.u32.u64 %0, t; }" : "=r"(a) : "l"(p));
    return a;
}
__device__ __forceinline__ void cp16(uint32_t d, const void* s) {
    asm volatile("cp.async.cg.shared.global [%0], [%1], 16;" :: "r"(d), "l"(s));
}
#define CP_COMMIT() asm volatile("cp.async.commit_group;" ::: "memory")
#define CP_WAIT(n)  asm volatile("cp.async.wait_group %0;" :: "n"(n) : "memory")
#define SWZ(o) ((o) ^ (((o) >> 3) & 0x70))

__device__ __forceinline__ void ldsm4(uint32_t& r0, uint32_t& r1, uint32_t& r2, uint32_t& r3,
                                      uint32_t addr) {
    asm volatile("ldmatrix.sync.aligned.m8n8.x4.shared.b16 {%0,%1,%2,%3}, [%4];"
                 : "=r"(r0), "=r"(r1), "=r"(r2), "=r"(r3) : "r"(addr));
}
__device__ __forceinline__ void mma16816(float* d, const uint32_t* a, const uint32_t* b) {
    asm volatile("mma.sync.aligned.m16n8k16.row.col.f32.f16.f16.f32 "
                 "{%0,%1,%2,%3}, {%4,%5,%6,%7}, {%8,%9}, {%0,%1,%2,%3};"
                 : "+f"(d[0]), "+f"(d[1]), "+f"(d[2]), "+f"(d[3])
                 : "r"(a[0]), "r"(a[1]), "r"(a[2]), "r"(a[3]), "r"(b[0]), "r"(b[1]));
}

// -------- prep kernels --------
__global__ __launch_bounds__(256) void k_convert_x(const float4* __restrict__ x4) {
    if (blockIdx.x == 0 && threadIdx.x == 0) g_fixcnt = 0;
    size_t i = (size_t)blockIdx.x * 256 + threadIdx.x;
    float4 v = x4[i];
    __half2* ph = reinterpret_cast<__half2*>(g_xh);
    ph[i * 2 + 0] = __floats2half2_rn(v.x, v.y);
    ph[i * 2 + 1] = __floats2half2_rn(v.z, v.w);
}

// proj f32 [K1][N1] -> g_projT fp16 [N1][K1]
__global__ __launch_bounds__(256) void k_transpose_proj(const float* __restrict__ src) {
    __shared__ float t[32][33];
    int c0 = blockIdx.x * 32, r0 = blockIdx.y * 32;
    int tx = threadIdx.x & 31, ty = threadIdx.x >> 5;
#pragma unroll
    for (int j = 0; j < 4; ++j)
        t[ty + j * 8][tx] = src[(size_t)(r0 + ty + j * 8) * N1 + c0 + tx];
    __syncthreads();
#pragma unroll
    for (int j = 0; j < 4; ++j) {
        int c = c0 + ty + j * 8;
        g_projT[(size_t)c * K1 + r0 + tx] = __float2half_rn(t[tx][ty + j * 8]);
    }
}

// chv f32 [N1][NC] -> g_chvT fp16 [NCP][N1], rows >= NC zero
__global__ __launch_bounds__(256) void k_transpose_chv(const float* __restrict__ src) {
    __shared__ float t[32][33];
    int c0 = blockIdx.x * 32, r0 = blockIdx.y * 32;
    int tx = threadIdx.x & 31, ty = threadIdx.x >> 5;
#pragma unroll
    for (int j = 0; j < 4; ++j) {
        int r = r0 + ty + j * 8, c = c0 + tx;
        t[ty + j * 8][tx] = (c < NC) ? src[(size_t)r * NC + c] : 0.f;
    }
    __syncthreads();
#pragma unroll
    for (int j = 0; j < 4; ++j) {
        int c = c0 + ty + j * 8;
        g_chvT[(size_t)c * N1 + r0 + tx] = __float2half_rn(t[tx][ty + j * 8]);
    }
}

// -------- fp16 HMMA GEMM: CTA 128x128, 256 thr, warps 2x4 (64x32), K-chunk 64, 3 stages,
// 2 CTAs/SM (launch_bounds(256,2) caps regs at 128) --------
// MODE 1: hv = x @ projT^T -> sign to outF (f32) + g_hvb (fp16); queue |hv| < TAU
// MODE 2: scores = g_hvb @ chvT^T -> guarded f32 store (cols < NC)
template<int MODE>
__global__ __launch_bounds__(256, 2) void hd_gemm(float* __restrict__ outF) {
    constexpr int  KTOT = (MODE == 1) ? K1 : N1;
    constexpr int  A_BYTES = 128 * 128;            // 128 rows x 64 fp16 (SW128, 16KB)
    constexpr int  STAGE_BYTES = 2 * A_BYTES;      // 32KB
    constexpr int  STAGES = 3;                     // 96KB total -> 2 CTAs/SM
    constexpr int  C = KTOT / 64;                  // 32 / 128

    extern __shared__ char smem[];
    const int tid = threadIdx.x;
    const int wid = tid >> 5, lane = tid & 31;
    const int wm = wid & 1, wn = wid >> 1;
    const int m0 = blockIdx.y * 128;
    const int n0 = blockIdx.x * 128;
    const uint32_t sb = smem_u32(smem);

    const __half* __restrict__ Am = (MODE == 1) ? g_xh : g_hvb;
    const __half* __restrict__ Bt = (MODE == 1) ? g_projT : g_chvT;

    float acc[4][4][4];
#pragma unroll
    for (int i = 0; i < 4; ++i)
#pragma unroll
        for (int j = 0; j < 4; ++j)
#pragma unroll
            for (int q = 0; q < 4; ++q) acc[i][j][q] = 0.f;

    auto load_stage = [&](int chunk, int st) {
        uint32_t base = sb + st * STAGE_BYTES;
#pragma unroll
        for (int i = 0; i < 4; ++i) {              // A: 128 rows x 8 x16B
            int u = tid + i * 256, r = u >> 3, cc = u & 7;
            cp16(base + SWZ(r * 128 + cc * 16),
                 Am + (size_t)(m0 + r) * KTOT + chunk * 64 + cc * 8);
        }
#pragma unroll
        for (int i = 0; i < 4; ++i) {              // B
            int u = tid + i * 256, r = u >> 3, cc = u & 7;
            cp16(base + A_BYTES + SWZ(r * 128 + cc * 16),
                 Bt + (size_t)(n0 + r) * KTOT + chunk * 64 + cc * 8);
        }
    };

    for (int p = 0; p < STAGES - 1; ++p) { load_stage(p, p); CP_COMMIT(); }

    const int a_row = lane & 15;
    const int a_cb  = (lane >> 4) << 4;
    const int b_row = ((lane >> 4) << 3) + (lane & 7);
    const int b_cb  = ((lane >> 3) & 1) << 4;

    for (int c = 0; c < C; ++c) {
        int st = c % STAGES;
        if (c < C - 1) { CP_WAIT(1); } else { CP_WAIT(0); }
        __syncthreads();
        int nxt = c + STAGES - 1;
        if (nxt < C) { load_stage(nxt, nxt % STAGES); CP_COMMIT(); }

        uint32_t aBase = sb + st * STAGE_BYTES;
        uint32_t bBase = aBase + A_BYTES;
#pragma unroll
        for (int ks = 0; ks < 4; ++ks) {
            int kb = ks * 32;
            uint32_t bfr[2][4];
#pragma unroll
            for (int j2 = 0; j2 < 2; ++j2) {
                int nrow = wn * 32 + j2 * 16 + b_row;
                ldsm4(bfr[j2][0], bfr[j2][1], bfr[j2][2], bfr[j2][3],
                      bBase + SWZ(nrow * 128 + kb + b_cb));
            }
#pragma unroll
            for (int i = 0; i < 4; ++i) {
                int mrow = wm * 64 + i * 16 + a_row;
                uint32_t afr[4];
                ldsm4(afr[0], afr[1], afr[2], afr[3],
                      aBase + SWZ(mrow * 128 + kb + a_cb));
#pragma unroll
                for (int j = 0; j < 4; ++j)
                    mma16816(acc[i][j], afr, &bfr[j >> 1][(j & 1) * 2]);
            }
        }
        __syncthreads();
    }

    // -------- epilogue --------
    const int gid = lane >> 2, tid4 = lane & 3;
#pragma unroll
    for (int i = 0; i < 4; ++i) {
#pragma unroll
        for (int half = 0; half < 2; ++half) {
            size_t row = m0 + wm * 64 + i * 16 + gid + half * 8;
#pragma unroll
            for (int j = 0; j < 4; ++j) {
                int col = n0 + wn * 32 + j * 8 + tid4 * 2;
                float v0 = acc[i][j][half * 2 + 0];
                float v1 = acc[i][j][half * 2 + 1];
                if (MODE == 1) {
                    float s0 = (v0 >= 0.f) ? 1.f : -1.f;
                    float s1 = (v1 >= 0.f) ? 1.f : -1.f;
                    *reinterpret_cast<float2*>(outF + row * (size_t)N1 + col) =
                        make_float2(s0, s1);
                    *reinterpret_cast<__half2*>(g_hvb + row * (size_t)N1 + col) =
                        __floats2half2_rn(s0, s1);
                    if (fabsf(v0) < TAU) {
                        uint32_t idx = atomicAdd(&g_fixcnt, 1u);
                        if (idx < FIXCAP) g_fixq[idx] = ((uint32_t)row << 13) | (uint32_t)col;
                    }
                    if (fabsf(v1) < TAU) {
                        uint32_t idx = atomicAdd(&g_fixcnt, 1u);
                        if (idx < FIXCAP) g_fixq[idx] = ((uint32_t)row << 13) | (uint32_t)(col + 1);
                    }
                } else {
                    if (col + 1 < NC) {
                        *reinterpret_cast<float2*>(outF + row * (size_t)NC + col) =
                            make_float2(v0, v1);
                    } else if (col < NC) {
                        outF[row * (size_t)NC + col] = v0;
                    }
                }
            }
        }
    }
}

// -------- exact fixup: warp per queued element, Kahan fp32 dot over K1 --------
__global__ __launch_bounds__(128) void k_fixup(const float* __restrict__ x,
                                               float* __restrict__ hvf32) {
    uint32_t total = g_fixcnt;
    if (total > FIXCAP) total = FIXCAP;
    int gw = (blockIdx.x * 128 + threadIdx.x) >> 5;
    int lane = threadIdx.x & 31;
    int nw = (gridDim.x * 128) >> 5;
    for (uint32_t w = gw; w < total; w += nw) {
        uint32_t e = g_fixq[w];
        uint32_t row = e >> 13, col = e & 8191u;
        const float* xr = x + (size_t)row * K1;
        const __half* pr = g_projT + (size_t)col * K1;
        float s = 0.f, comp = 0.f;
#pragma unroll 4
        for (int j = 0; j < K1 / 32; ++j) {
            int k = lane + j * 32;
            float t = xr[k] * __half2float(pr[k]);
            float y = t - comp;
            float u = s + y;
            comp = (u - s) - y;
            s = u;
        }
#pragma unroll
        for (int o = 16; o > 0; o >>= 1) s += __shfl_xor_sync(0xFFFFFFFFu, s, o);
        if (lane == 0) {
            float sg = (s >= 0.f) ? 1.f : -1.f;
            hvf32[(size_t)row * N1 + col] = sg;
            g_hvb[(size_t)row * N1 + col] = __float2half_rn(sg);
        }
    }
}

// -------- launch --------
extern "C" void kernel_launch(void* const* d_in, const int* in_sizes, int n_in,
                              void* d_out, int out_size)
{
    const float* x    = (const float*)d_in[0];
    const float* proj = (const float*)d_in[1];
    const float* chv  = (const float*)d_in[2];
    float* scores = (float*)d_out;
    float* hvf32  = (float*)d_out + SCORES_ELEMS;

    constexpr int SMB = 3 * 2 * 128 * 128;   // 98304 (3 stages x 32KB) -> 2 CTAs/SM
    cudaFuncSetAttribute(hd_gemm<1>, cudaFuncAttributeMaxDynamicSharedMemorySize, SMB);
    cudaFuncSetAttribute(hd_gemm<2>, cudaFuncAttributeMaxDynamicSharedMemorySize, SMB);

    k_convert_x<<<32768, 256>>>((const float4*)x);
    k_transpose_proj<<<dim3(N1 / 32, K1 / 32), 256>>>(proj);
    k_transpose_chv<<<dim3(NCP / 32, N1 / 32), 256>>>(chv);

    hd_gemm<1><<<dim3(N1 / 128, M1 / 128), 256, SMB>>>(hvf32);   // single fp16 pass
    k_fixup<<<2048, 128>>>(x, hvf32);
    hd_gemm<2><<<dim3(NCP / 128, M1 / 128), 256, SMB>>>(scores);
}

// round 16
// speedup vs baseline: 1.2261x; 1.0261x over previous
#include <cuda_runtime.h>
#include <cuda_fp16.h>
#include <cstdint>

// HDCHead: scores = sign(x@proj) @ class_hv ; outputs (scores[16384,1000], hv_bin[16384,8192]) f32.
// R15: R14 base (fp16 single-pass, 128x128 CTA, 64x32 warps, K-chunk 64, 3 stages, 2 CTAs/SM)
// + TAU=0.03 fixup + streaming (evict-first) epilogue stores.

static constexpr int M1 = 16384, K1 = 2048, N1 = 8192, NC = 1000, NCP = 1024;
static constexpr long long SCORES_ELEMS = (long long)M1 * NC;
static constexpr float TAU = 0.03f;
static constexpr uint32_t FIXCAP = 1u << 21;

// -------- scratch (device globals) --------
__device__ __align__(256) __half g_xh[(size_t)M1 * K1];      //  67MB
__device__ __align__(256) __half g_projT[(size_t)N1 * K1];   //  33MB  [N1][K1]
__device__ __align__(256) __half g_chvT[(size_t)NCP * N1];   //  17MB  [1024][8192]
__device__ __align__(256) __half g_hvb[(size_t)M1 * N1];     // 268MB  fp16 sign
__device__ uint32_t g_fixcnt;
__device__ uint32_t g_fixq[FIXCAP];

// -------- PTX helpers --------
__device__ __forceinline__ uint32_t smem_u32(const void* p) {
    uint32_t a;
    asm("{ .reg .u64 t; cvta.to.shared.u64 t, %1; cvt.u32.u64 %0, t; }" : "=r"(a) : "l"(p));
    return a;
}
__device__ __forceinline__ void cp16(uint32_t d, const void* s) {
    asm volatile("cp.async.cg.shared.global [%0], [%1], 16;" :: "r"(d), "l"(s));
}
#define CP_COMMIT() asm volatile("cp.async.commit_group;" ::: "memory")
#define CP_WAIT(n)  asm volatile("cp.async.wait_group %0;" :: "n"(n) : "memory")
#define SWZ(o) ((o) ^ (((o) >> 3) & 0x70))

__device__ __forceinline__ void ldsm4(uint32_t& r0, uint32_t& r1, uint32_t& r2, uint32_t& r3,
                                      uint32_t addr) {
    asm volatile("ldmatrix.sync.aligned.m8n8.x4.shared.b16 {%0,%1,%2,%3}, [%4];"
                 : "=r"(r0), "=r"(r1), "=r"(r2), "=r"(r3) : "r"(addr));
}
__device__ __forceinline__ void mma16816(float* d, const uint32_t* a, const uint32_t* b) {
    asm volatile("mma.sync.aligned.m16n8k16.row.col.f32.f16.f16.f32 "
                 "{%0,%1,%2,%3}, {%4,%5,%6,%7}, {%8,%9}, {%0,%1,%2,%3};"
                 : "+f"(d[0]), "+f"(d[1]), "+f"(d[2]), "+f"(d[3])
                 : "r"(a[0]), "r"(a[1]), "r"(a[2]), "r"(a[3]), "r"(b[0]), "r"(b[1]));
}
__device__ __forceinline__ void stcs_v2f32(float* p, float a, float b) {
    asm volatile("st.global.cs.v2.f32 [%0], {%1, %2};" :: "l"(p), "f"(a), "f"(b) : "memory");
}
__device__ __forceinline__ void stcs_b32(void* p, uint32_t v) {
    asm volatile("st.global.cs.b32 [%0], %1;" :: "l"(p), "r"(v) : "memory");
}

// -------- prep kernels --------
__global__ __launch_bounds__(256) void k_convert_x(const float4* __restrict__ x4) {
    if (blockIdx.x == 0 && threadIdx.x == 0) g_fixcnt = 0;
    size_t i = (size_t)blockIdx.x * 256 + threadIdx.x;
    float4 v = x4[i];
    __half2* ph = reinterpret_cast<__half2*>(g_xh);
    ph[i * 2 + 0] = __floats2half2_rn(v.x, v.y);
    ph[i * 2 + 1] = __floats2half2_rn(v.z, v.w);
}

// proj f32 [K1][N1] -> g_projT fp16 [N1][K1]
__global__ __launch_bounds__(256) void k_transpose_proj(const float* __restrict__ src) {
    __shared__ float t[32][33];
    int c0 = blockIdx.x * 32, r0 = blockIdx.y * 32;
    int tx = threadIdx.x & 31, ty = threadIdx.x >> 5;
#pragma unroll
    for (int j = 0; j < 4; ++j)
        t[ty + j * 8][tx] = src[(size_t)(r0 + ty + j * 8) * N1 + c0 + tx];
    __syncthreads();
#pragma unroll
    for (int j = 0; j < 4; ++j) {
        int c = c0 + ty + j * 8;
        g_projT[(size_t)c * K1 + r0 + tx] = __float2half_rn(t[tx][ty + j * 8]);
    }
}

// chv f32 [N1][NC] -> g_chvT fp16 [NCP][N1], rows >= NC zero
__global__ __launch_bounds__(256) void k_transpose_chv(const float* __restrict__ src) {
    __shared__ float t[32][33];
    int c0 = blockIdx.x * 32, r0 = blockIdx.y * 32;
    int tx = threadIdx.x & 31, ty = threadIdx.x >> 5;
#pragma unroll
    for (int j = 0; j < 4; ++j) {
        int r = r0 + ty + j * 8, c = c0 + tx;
        t[ty + j * 8][tx] = (c < NC) ? src[(size_t)r * NC + c] : 0.f;
    }
    __syncthreads();
#pragma unroll
    for (int j = 0; j < 4; ++j) {
        int c = c0 + ty + j * 8;
        g_chvT[(size_t)c * N1 + r0 + tx] = __float2half_rn(t[tx][ty + j * 8]);
    }
}

// -------- fp16 HMMA GEMM: CTA 128x128, 256 thr, warps 2x4 (64x32), K-chunk 64, 3 stages,
// 2 CTAs/SM --------
// MODE 1: hv = x @ projT^T -> sign to outF (f32, streaming) + g_hvb (fp16, streaming);
//         queue |hv| < TAU
// MODE 2: scores = g_hvb @ chvT^T -> guarded f32 store (cols < NC)
template<int MODE>
__global__ __launch_bounds__(256, 2) void hd_gemm(float* __restrict__ outF) {
    constexpr int  KTOT = (MODE == 1) ? K1 : N1;
    constexpr int  A_BYTES = 128 * 128;            // 128 rows x 64 fp16 (SW128, 16KB)
    constexpr int  STAGE_BYTES = 2 * A_BYTES;      // 32KB
    constexpr int  STAGES = 3;                     // 96KB -> 2 CTAs/SM
    constexpr int  C = KTOT / 64;                  // 32 / 128

    extern __shared__ char smem[];
    const int tid = threadIdx.x;
    const int wid = tid >> 5, lane = tid & 31;
    const int wm = wid & 1, wn = wid >> 1;
    const int m0 = blockIdx.y * 128;
    const int n0 = blockIdx.x * 128;
    const uint32_t sb = smem_u32(smem);

    const __half* __restrict__ Am = (MODE == 1) ? g_xh : g_hvb;
    const __half* __restrict__ Bt = (MODE == 1) ? g_projT : g_chvT;

    float acc[4][4][4];
#pragma unroll
    for (int i = 0; i < 4; ++i)
#pragma unroll
        for (int j = 0; j < 4; ++j)
#pragma unroll
            for (int q = 0; q < 4; ++q) acc[i][j][q] = 0.f;

    auto load_stage = [&](int chunk, int st) {
        uint32_t base = sb + st * STAGE_BYTES;
#pragma unroll
        for (int i = 0; i < 4; ++i) {              // A
            int u = tid + i * 256, r = u >> 3, cc = u & 7;
            cp16(base + SWZ(r * 128 + cc * 16),
                 Am + (size_t)(m0 + r) * KTOT + chunk * 64 + cc * 8);
        }
#pragma unroll
        for (int i = 0; i < 4; ++i) {              // B
            int u = tid + i * 256, r = u >> 3, cc = u & 7;
            cp16(base + A_BYTES + SWZ(r * 128 + cc * 16),
                 Bt + (size_t)(n0 + r) * KTOT + chunk * 64 + cc * 8);
        }
    };

    for (int p = 0; p < STAGES - 1; ++p) { load_stage(p, p); CP_COMMIT(); }

    const int a_row = lane & 15;
    const int a_cb  = (lane >> 4) << 4;
    const int b_row = ((lane >> 4) << 3) + (lane & 7);
    const int b_cb  = ((lane >> 3) & 1) << 4;

    for (int c = 0; c < C; ++c) {
        int st = c % STAGES;
        if (c < C - 1) { CP_WAIT(1); } else { CP_WAIT(0); }
        __syncthreads();
        int nxt = c + STAGES - 1;
        if (nxt < C) { load_stage(nxt, nxt % STAGES); CP_COMMIT(); }

        uint32_t aBase = sb + st * STAGE_BYTES;
        uint32_t bBase = aBase + A_BYTES;
#pragma unroll
        for (int ks = 0; ks < 4; ++ks) {
            int kb = ks * 32;
            uint32_t bfr[2][4];
#pragma unroll
            for (int j2 = 0; j2 < 2; ++j2) {
                int nrow = wn * 32 + j2 * 16 + b_row;
                ldsm4(bfr[j2][0], bfr[j2][1], bfr[j2][2], bfr[j2][3],
                      bBase + SWZ(nrow * 128 + kb + b_cb));
            }
#pragma unroll
            for (int i = 0; i < 4; ++i) {
                int mrow = wm * 64 + i * 16 + a_row;
                uint32_t afr[4];
                ldsm4(afr[0], afr[1], afr[2], afr[3],
                      aBase + SWZ(mrow * 128 + kb + a_cb));
#pragma unroll
                for (int j = 0; j < 4; ++j)
                    mma16816(acc[i][j], afr, &bfr[j >> 1][(j & 1) * 2]);
            }
        }
        __syncthreads();
    }

    // -------- epilogue --------
    const int gid = lane >> 2, tid4 = lane & 3;
#pragma unroll
    for (int i = 0; i < 4; ++i) {
#pragma unroll
        for (int half = 0; half < 2; ++half) {
            size_t row = m0 + wm * 64 + i * 16 + gid + half * 8;
#pragma unroll
            for (int j = 0; j < 4; ++j) {
                int col = n0 + wn * 32 + j * 8 + tid4 * 2;
                float v0 = acc[i][j][half * 2 + 0];
                float v1 = acc[i][j][half * 2 + 1];
                if (MODE == 1) {
                    float s0 = (v0 >= 0.f) ? 1.f : -1.f;
                    float s1 = (v1 >= 0.f) ? 1.f : -1.f;
                    stcs_v2f32(outF + row * (size_t)N1 + col, s0, s1);
                    __half2 h2 = __floats2half2_rn(s0, s1);
                    stcs_b32(g_hvb + row * (size_t)N1 + col,
                             *reinterpret_cast<uint32_t*>(&h2));
                    if (fabsf(v0) < TAU) {
                        uint32_t idx = atomicAdd(&g_fixcnt, 1u);
                        if (idx < FIXCAP) g_fixq[idx] = ((uint32_t)row << 13) | (uint32_t)col;
                    }
                    if (fabsf(v1) < TAU) {
                        uint32_t idx = atomicAdd(&g_fixcnt, 1u);
                        if (idx < FIXCAP) g_fixq[idx] = ((uint32_t)row << 13) | (uint32_t)(col + 1);
                    }
                } else {
                    if (col + 1 < NC) {
                        *reinterpret_cast<float2*>(outF + row * (size_t)NC + col) =
                            make_float2(v0, v1);
                    } else if (col < NC) {
                        outF[row * (size_t)NC + col] = v0;
                    }
                }
            }
        }
    }
}

// -------- exact fixup: warp per queued element, Kahan fp32 dot over K1 --------
__global__ __launch_bounds__(128) void k_fixup(const float* __restrict__ x,
                                               float* __restrict__ hvf32) {
    uint32_t total = g_fixcnt;
    if (total > FIXCAP) total = FIXCAP;
    int gw = (blockIdx.x * 128 + threadIdx.x) >> 5;
    int lane = threadIdx.x & 31;
    int nw = (gridDim.x * 128) >> 5;
    for (uint32_t w = gw; w < total; w += nw) {
        uint32_t e = g_fixq[w];
        uint32_t row = e >> 13, col = e & 8191u;
        const float* xr = x + (size_t)row * K1;
        const __half* pr = g_projT + (size_t)col * K1;
        float s = 0.f, comp = 0.f;
#pragma unroll 4
        for (int j = 0; j < K1 / 32; ++j) {
            int k = lane + j * 32;
            float t = xr[k] * __half2float(pr[k]);
            float y = t - comp;
            float u = s + y;
            comp = (u - s) - y;
            s = u;
        }
#pragma unroll
        for (int o = 16; o > 0; o >>= 1) s += __shfl_xor_sync(0xFFFFFFFFu, s, o);
        if (lane == 0) {
            float sg = (s >= 0.f) ? 1.f : -1.f;
            hvf32[(size_t)row * N1 + col] = sg;
            g_hvb[(size_t)row * N1 + col] = __float2half_rn(sg);
        }
    }
}

// -------- launch --------
extern "C" void kernel_launch(void* const* d_in, const int* in_sizes, int n_in,
                              void* d_out, int out_size)
{
    const float* x    = (const float*)d_in[0];
    const float* proj = (const float*)d_in[1];
    const float* chv  = (const float*)d_in[2];
    float* scores = (float*)d_out;
    float* hvf32  = (float*)d_out + SCORES_ELEMS;

    constexpr int SMB = 3 * 2 * 128 * 128;   // 98304 -> 2 CTAs/SM
    cudaFuncSetAttribute(hd_gemm<1>, cudaFuncAttributeMaxDynamicSharedMemorySize, SMB);
    cudaFuncSetAttribute(hd_gemm<2>, cudaFuncAttributeMaxDynamicSharedMemorySize, SMB);

    k_convert_x<<<32768, 256>>>((const float4*)x);
    k_transpose_proj<<<dim3(N1 / 32, K1 / 32), 256>>>(proj);
    k_transpose_chv<<<dim3(NCP / 32, N1 / 32), 256>>>(chv);

    hd_gemm<1><<<dim3(N1 / 128, M1 / 128), 256, SMB>>>(hvf32);   // single fp16 pass
    k_fixup<<<2048, 128>>>(x, hvf32);
    hd_gemm<2><<<dim3(NCP / 128, M1 / 128), 256, SMB>>>(scores);
}